// round 15
// baseline (speedup 1.0000x reference)
#include <cuda_runtime.h>
#include <cuda_bf16.h>
#include <cuda_fp16.h>
#include <cstdint>

#define EMBED 1024
#define NHEAD 16
#define HDIM  64
#define BATCH 2
#define SEQ   2048
#define MROWS (BATCH*SEQ)   // 4096

// ---------------------------------------------------------------------------
// Device-global scratch — single fp16 everywhere.
// Q pre-scaled by 0.125*log2(e) (base-2 softmax domain).
// ---------------------------------------------------------------------------
__device__ __half g_xf [MROWS*EMBED];                           // x  [m][k]
__device__ __half g_wf [4*EMBED*EMBED];                         // W^T [4][n][k]
__device__ __half g_qf [BATCH*NHEAD*SEQ*HDIM];                  // [b,h,s,d]
__device__ __half g_kf [BATCH*NHEAD*SEQ*HDIM];                  // [b,h,s,d]
__device__ __half g_vf [BATCH*NHEAD*HDIM*SEQ];                  // [b,h,d,s]
__device__ __half g_cf [MROWS*EMBED];                           // ctx [m][e]

// ---------------------------------------------------------------------------
// Helpers
// ---------------------------------------------------------------------------
__device__ __forceinline__ uint32_t smem_u32(const void* p) {
    uint32_t a;
    asm("{ .reg .u64 t; cvta.to.shared.u64 t, %1; cvt.u32.u64 %0, t; }"
        : "=r"(a) : "l"(p));
    return a;
}
__device__ __forceinline__ uint32_t pk2h(float e0, float e1) {  // f16x2, e0 low
    uint32_t d;
    asm("cvt.rn.f16x2.f32 %0, %1, %2;" : "=r"(d) : "f"(e1), "f"(e0));
    return d;
}
__device__ __forceinline__ float ex2(float x) {
    float r;
    asm("ex2.approx.f32 %0, %1;" : "=f"(r) : "f"(x));
    return r;
}
__device__ __forceinline__ uint32_t ex2h2(uint32_t x) {         // 2x fp16 exp2
    uint32_t d;
    asm("ex2.approx.f16x2 %0, %1;" : "=r"(d) : "r"(x));
    return d;
}

#define MMAF16(c, a, b0, b1)                                                \
    asm("mma.sync.aligned.m16n8k16.row.col.f32.f16.f16.f32 "                \
        "{%0,%1,%2,%3}, {%4,%5,%6,%7}, {%8,%9}, {%0,%1,%2,%3};"             \
        : "+f"((c)[0]), "+f"((c)[1]), "+f"((c)[2]), "+f"((c)[3])            \
        : "r"((a)[0]), "r"((a)[1]), "r"((a)[2]), "r"((a)[3]),               \
          "r"(b0), "r"(b1))

#define CP_ASYNC16(dst, src)                                                \
    asm volatile("cp.async.cg.shared.global [%0], [%1], 16;"                \
        :: "r"(dst), "l"(src) : "memory")
#define CP_COMMIT() asm volatile("cp.async.commit_group;" ::: "memory")
#define CP_WAIT(n)  asm volatile("cp.async.wait_group %0;" :: "n"(n) : "memory")

#define QSCALE 0.180336880111120419f   // 0.125 * log2(e)

// ---------------------------------------------------------------------------
// Conversion kernels
// ---------------------------------------------------------------------------
extern "C" __global__ void __launch_bounds__(256)
cvt_x_kernel(const float* __restrict__ src)
{
    int i = (blockIdx.x * 256 + threadIdx.x) * 4;
    float4 v = *reinterpret_cast<const float4*>(src + i);
    *reinterpret_cast<uint2*>(g_xf + i) =
        make_uint2(pk2h(v.x, v.y), pk2h(v.z, v.w));
}

extern "C" __global__ void __launch_bounds__(256)
cvt_w_kernel(const float* __restrict__ Wq, const float* __restrict__ Wk,
             const float* __restrict__ Wv, const float* __restrict__ Wo)
{
    __shared__ float t[32][33];
    const float* W = (blockIdx.z == 0) ? Wq : (blockIdx.z == 1) ? Wk :
                     (blockIdx.z == 2) ? Wv : Wo;
    __half* of = g_wf + (size_t)blockIdx.z * EMBED * EMBED;
    int bx = blockIdx.x * 32;  // n base
    int by = blockIdx.y * 32;  // k base
    int tx = threadIdx.x, ty = threadIdx.y;
#pragma unroll
    for (int i = 0; i < 4; i++) {
        int r = ty + i * 8;
        t[r][tx] = W[(size_t)(by + r) * EMBED + bx + tx];
    }
    __syncthreads();
#pragma unroll
    for (int i = 0; i < 4; i++) {
        int r = ty + i * 8;
        of[(size_t)(bx + r) * EMBED + by + tx] = __float2half_rn(t[tx][r]);
    }
}

// ---------------------------------------------------------------------------
// fp16 GEMM (projections): 128x128 tile, 128 threads (2x2 warps), 2 CTAs/SM
// — unchanged from R14.
// ---------------------------------------------------------------------------
#define GTH 128
#define GWT (128*36)
#define GBUF (2*GWT)
#define GSMEM2 (2*GBUF*4)                // 73728 B

__device__ __forceinline__ void gemm_stage(
    uint32_t swb, int buf, int tid,
    const __half* sA, const __half* sB, int k0)
{
    const uint32_t dbase = swb + (uint32_t)(buf * GBUF) * 4;
#pragma unroll
    for (int j = 0; j < 8; j++) {
        int idx = tid + j * GTH;
        int r = idx >> 3, c = idx & 7;
        uint32_t doff = (uint32_t)(r * 36 + c * 4) * 4;
        CP_ASYNC16(dbase + doff, sA + (size_t)r * EMBED + k0 + c * 8);
    }
#pragma unroll
    for (int j = 0; j < 8; j++) {
        int idx = tid + j * GTH;
        int r = idx >> 3, c = idx & 7;
        uint32_t doff = (uint32_t)(GWT + r * 36 + c * 4) * 4;
        CP_ASYNC16(dbase + doff, sB + (size_t)r * EMBED + k0 + c * 8);
    }
}

__device__ __forceinline__ void gemm_mma_body(
    const __half* __restrict__ A, const __half* __restrict__ B,
    const float* __restrict__ bias, int mode, float* __restrict__ outf, float scale)
{
    extern __shared__ uint32_t sw[];
    const uint32_t swb = smem_u32(sw);
    const int tid = threadIdx.x;
    const int lane = tid & 31, wid = tid >> 5;
    const int g = lane >> 2, t = lane & 3;
    const int wm = wid & 1, wn = wid >> 1;
    const int m0 = blockIdx.y * 128, n0 = blockIdx.x * 128;

    const __half* sA = A + (size_t)m0 * EMBED;
    const __half* sB = B + (size_t)n0 * EMBED;

    float acc[4][8][4];
#pragma unroll
    for (int a = 0; a < 4; a++)
#pragma unroll
        for (int b = 0; b < 8; b++)
#pragma unroll
            for (int c = 0; c < 4; c++) acc[a][b][c] = 0.f;

    gemm_stage(swb, 0, tid, sA, sB, 0);
    CP_COMMIT();

    for (int it = 0; it < 16; it++) {
        const int buf = it & 1;
        __syncthreads();
        if (it + 1 < 16) {
            gemm_stage(swb, buf ^ 1, tid, sA, sB, (it + 1) * 64);
            CP_COMMIT();
            CP_WAIT(1);
        } else {
            CP_WAIT(0);
        }
        __syncthreads();

        uint32_t* As = sw + buf * GBUF;
        uint32_t* Bs = As + GWT;

#pragma unroll
        for (int ks = 0; ks < 4; ks++) {
            uint32_t ah[4][4];
#pragma unroll
            for (int mt = 0; mt < 4; mt++) {
                int r = wm * 64 + mt * 16 + g;
                int base = r * 36 + ks * 8 + t;
                ah[mt][0] = As[base];     ah[mt][1] = As[base + 8*36];
                ah[mt][2] = As[base + 4]; ah[mt][3] = As[base + 8*36 + 4];
            }
#pragma unroll
            for (int ntp = 0; ntp < 4; ntp++) {
                uint32_t b0[2], b1[2];
#pragma unroll
                for (int q = 0; q < 2; q++) {
                    int n = wn * 64 + (2 * ntp + q) * 8 + g;
                    int base = n * 36 + ks * 8 + t;
                    b0[q] = Bs[base]; b1[q] = Bs[base + 4];
                }
#pragma unroll
                for (int q = 0; q < 2; q++)
#pragma unroll
                    for (int mt = 0; mt < 4; mt++)
                        MMAF16(acc[mt][2*ntp+q], ah[mt], b0[q], b1[q]);
            }
        }
    }

    // epilogue
#pragma unroll
    for (int mt = 0; mt < 4; mt++) {
#pragma unroll
        for (int nt = 0; nt < 8; nt++) {
            int r0 = m0 + wm * 64 + mt * 16 + g;
            int r1 = r0 + 8;
            int c0 = n0 + wn * 64 + nt * 8 + 2 * t;
            float2 bb = *reinterpret_cast<const float2*>(&bias[c0]);
            float v0 = (acc[mt][nt][0] + bb.x) * scale;
            float v1 = (acc[mt][nt][1] + bb.y) * scale;
            float v2 = (acc[mt][nt][2] + bb.x) * scale;
            float v3 = (acc[mt][nt][3] + bb.y) * scale;
            if (mode == 0) {
                *reinterpret_cast<float2*>(&outf[(size_t)r0 * EMBED + c0]) = make_float2(v0, v1);
                *reinterpret_cast<float2*>(&outf[(size_t)r1 * EMBED + c0]) = make_float2(v2, v3);
            } else {
                int hh = c0 >> 6, d = c0 & 63;
                int b0i = r0 >> 11, s0i = r0 & (SEQ - 1);
                int b1i = r1 >> 11, s1i = r1 & (SEQ - 1);
                if (mode <= 2) {
                    __half* dst = (mode == 1) ? g_qf : g_kf;
                    size_t o0 = ((size_t)(b0i*NHEAD+hh)*SEQ + s0i)*HDIM + d;
                    size_t o1 = ((size_t)(b1i*NHEAD+hh)*SEQ + s1i)*HDIM + d;
                    *reinterpret_cast<uint32_t*>(dst + o0) = pk2h(v0, v1);
                    *reinterpret_cast<uint32_t*>(dst + o1) = pk2h(v2, v3);
                } else {
                    size_t base0 = (size_t)(b0i*NHEAD+hh)*HDIM*SEQ;
                    size_t base1 = (size_t)(b1i*NHEAD+hh)*HDIM*SEQ;
                    g_vf[base0 + (size_t)d * SEQ + s0i]     = __float2half_rn(v0);
                    g_vf[base0 + (size_t)(d+1) * SEQ + s0i] = __float2half_rn(v1);
                    g_vf[base1 + (size_t)d * SEQ + s1i]     = __float2half_rn(v2);
                    g_vf[base1 + (size_t)(d+1) * SEQ + s1i] = __float2half_rn(v3);
                }
            }
        }
    }
}

extern "C" __global__ void __launch_bounds__(GTH, 2)
qkv_mma_kernel(const float* __restrict__ bq, const float* __restrict__ bk,
               const float* __restrict__ bv)
{
    const int z = blockIdx.z;
    const __half* B = g_wf + (size_t)z * EMBED * EMBED;
    const float* bias = (z == 0) ? bq : (z == 1) ? bk : bv;
    int mode = (z == 0) ? 1 : (z == 1) ? 2 : 3;
    float scale = (z == 0) ? QSCALE : 1.0f;
    gemm_mma_body(g_xf, B, bias, mode, nullptr, scale);
}

extern "C" __global__ void __launch_bounds__(GTH, 2)
oproj_mma_kernel(const float* __restrict__ bo, float* __restrict__ out)
{
    gemm_mma_body(g_cf, g_wf + (size_t)3 * EMBED * EMBED, bo, 0, out, 1.0f);
}

// ---------------------------------------------------------------------------
// Flash attention — 128-thread CTAs, q-tile 64, **3 CTAs per SM**.
// Register diet: transient ph (per-j exp), plain fragment loads (no register
// prefetch), mask via L2-cached LDG (no smem copy). NBUF=2.
// Numerics identical to R13/R14 -> rel_err must remain 7.4263e-4.
// ---------------------------------------------------------------------------
#define ATH 128
#define KW (128*36)
#define VW2 (72*68)
#define ABUFW (KW + VW2)                 // 9504 words per buffer
#define ASMEM2 (2*ABUFW*4)               // 76032 B (x3 CTAs = 228096)

__device__ __forceinline__ void attn_stage_kv(
    uint32_t swb, int buf, int tid,
    const __half* kf, const __half* vf, int s0)
{
    const uint32_t dbase = swb + (uint32_t)(buf * ABUFW) * 4;
#pragma unroll
    for (int j = 0; j < 8; j++) {
        int idx = tid + j * ATH;
        {
            int r = idx >> 3, c = idx & 7;
            uint32_t doff = (uint32_t)(r * 36 + c * 4) * 4;
            CP_ASYNC16(dbase + doff, kf + (size_t)(s0 + r) * HDIM + c * 8);
        }
        {
            int d = idx >> 4, c = idx & 15;
            uint32_t doff = (uint32_t)(KW + d * 68 + c * 4) * 4;
            CP_ASYNC16(dbase + doff, vf + (size_t)d * SEQ + s0 + c * 8);
        }
    }
}

extern "C" __global__ void __launch_bounds__(ATH, 3)
attn_mma_kernel(const int* __restrict__ mask)
{
    extern __shared__ uint32_t sw[];
    const uint32_t swb = smem_u32(sw);

    const int tid = threadIdx.x, lane = tid & 31, wid = tid >> 5;
    const int g = lane >> 2, t = lane & 3;
    const int b = blockIdx.z, h = blockIdx.y;
    const int q0 = blockIdx.x * 64;
    const int qw = wid * 16;
    const size_t bh = (size_t)(b * NHEAD + h);
    const __half* qfp = g_qf + bh * SEQ * HDIM;
    const __half* kfp = g_kf + bh * SEQ * HDIM;
    const __half* vfp = g_vf + bh * HDIM * SEQ;
    const int* mb = mask + b * SEQ;

    // ones-row (row 64 = 1.0) and zero rows (65..71), both buffers
    for (int i = tid; i < 2 * 8 * 68; i += ATH) {
        int bufi = i / (8 * 68);
        int rr = (i / 68) % 8;
        int cc = i % 68;
        sw[bufi * ABUFW + KW + (64 + rr) * 68 + cc] =
            (rr == 0) ? 0x3C003C00u : 0u;
    }

    // stage Q (64 rows) into buf0 K-area, extract fragments
#pragma unroll
    for (int j = 0; j < 4; j++) {
        int idx = tid + j * ATH;
        int r = idx >> 3, c = idx & 7;
        uint32_t doff = (uint32_t)(r * 36 + c * 4) * 4;
        CP_ASYNC16(swb + doff, qfp + (size_t)(q0 + r) * HDIM + c * 8);
    }
    CP_COMMIT();
    CP_WAIT(0);
    __syncthreads();

    uint32_t qh[4][4];
#pragma unroll
    for (int ks = 0; ks < 4; ks++) {
#pragma unroll
        for (int p = 0; p < 4; p++) {
            int row = qw + g + ((p & 1) ? 8 : 0);
            int col = ks * 8 + t + ((p >= 2) ? 4 : 0);
            qh[ks][p] = sw[row * 36 + col];
        }
    }
    __syncthreads();

    attn_stage_kv(swb, 0, tid, kfp, vfp, 0);
    CP_COMMIT();

    float mrow[2] = {-1e30f, -1e30f};
    float o[8][4], ol[4];
#pragma unroll
    for (int i = 0; i < 8; i++)
#pragma unroll
        for (int j = 0; j < 4; j++) o[i][j] = 0.f;
#pragma unroll
    for (int j = 0; j < 4; j++) ol[j] = 0.f;

    for (int it = 0; it < 16; it++) {
        const int buf = it & 1;
        const int s0 = it * 128;
        __syncthreads();
        if (it + 1 < 16) {
            attn_stage_kv(swb, buf ^ 1, tid, kfp, vfp, (it + 1) * 128);
            CP_COMMIT();
            CP_WAIT(1);
        } else {
            CP_WAIT(0);
        }
        __syncthreads();

        uint32_t* Ksh = sw + buf * ABUFW;
        uint32_t* Vth = Ksh + KW;

        // ---- S = Q K^T (plain grouped loads, 4 independent accs per pass)
        float sc[16][4];
#pragma unroll
        for (int nt = 0; nt < 16; nt++)
#pragma unroll
            for (int j = 0; j < 4; j++) sc[nt][j] = 0.f;
#pragma unroll
        for (int ks = 0; ks < 4; ks++) {
#pragma unroll
            for (int ng = 0; ng < 4; ng++) {
                uint32_t b0[4], b1[4];
#pragma unroll
                for (int q = 0; q < 4; q++) {
                    int base = ((ng * 4 + q) * 8 + g) * 36 + ks * 8 + t;
                    b0[q] = Ksh[base]; b1[q] = Ksh[base + 4];
                }
#pragma unroll
                for (int q = 0; q < 4; q++)
                    MMAF16(sc[ng * 4 + q], qh[ks], b0[q], b1[q]);
            }
        }

        // ---- mask via L2-cached LDG (int2 per nt)
#pragma unroll
        for (int nt = 0; nt < 16; nt++) {
            int2 mv = __ldg(reinterpret_cast<const int2*>(&mb[s0 + nt * 8 + 2 * t]));
            if (mv.x == 0) { sc[nt][0] = -1e30f; sc[nt][2] = -1e30f; }
            if (mv.y == 0) { sc[nt][1] = -1e30f; sc[nt][3] = -1e30f; }
        }

        // ---- online max + rescale (sum via MMA ones-column)
        float alpha[2];
#pragma unroll
        for (int rh = 0; rh < 2; rh++) {
            float mt_ = -1e30f;
#pragma unroll
            for (int nt = 0; nt < 16; nt++)
                mt_ = fmaxf(mt_, fmaxf(sc[nt][rh * 2 + 0], sc[nt][rh * 2 + 1]));
            mt_ = fmaxf(mt_, __shfl_xor_sync(0xffffffffu, mt_, 1));
            mt_ = fmaxf(mt_, __shfl_xor_sync(0xffffffffu, mt_, 2));
            float mn = fmaxf(mrow[rh], mt_);
            alpha[rh] = ex2(mrow[rh] - mn);
            mrow[rh] = mn;
        }
#pragma unroll
        for (int dt = 0; dt < 8; dt++) {
            o[dt][0] *= alpha[0]; o[dt][1] *= alpha[0];
            o[dt][2] *= alpha[1]; o[dt][3] *= alpha[1];
        }
        ol[0] *= alpha[0]; ol[1] *= alpha[0];
        ol[2] *= alpha[1]; ol[3] *= alpha[1];

        // ---- O += P V  (transient ph per j; l via ones-row tile)
#pragma unroll
        for (int j = 0; j < 8; j++) {
            uint32_t ph[4];
#pragma unroll
            for (int p = 0; p < 4; p++) {
                int nt = 2 * j + (p >> 1);
                int rh = p & 1;
                int ix = rh * 2;
                ph[p] = ex2h2(pk2h(sc[nt][ix]     - mrow[rh],
                                   sc[nt][ix + 1] - mrow[rh]));
            }
#pragma unroll
            for (int dg = 0; dg < 2; dg++) {
                uint32_t v0[4], v1[4];
#pragma unroll
                for (int q = 0; q < 4; q++) {
                    int base = ((dg * 4 + q) * 8 + g) * 68 + j * 8 + t;
                    v0[q] = Vth[base]; v1[q] = Vth[base + 4];
                }
#pragma unroll
                for (int q = 0; q < 4; q++)
                    MMAF16(o[dg * 4 + q], ph, v0[q], v1[q]);
            }
            {
                int base = (64 + g) * 68 + j * 8 + t;
                MMAF16(ol, ph, Vth[base], Vth[base + 4]);
            }
        }
    }

    // ---- epilogue
    float l0 = __shfl_sync(0xffffffffu, ol[0], lane & 28);
    float l1 = __shfl_sync(0xffffffffu, ol[2], lane & 28);
    float inv0 = (l0 > 0.f) ? (1.f / l0) : 0.f;
    float inv1 = (l1 > 0.f) ? (1.f / l1) : 0.f;
    int r0 = q0 + qw + g, r1 = r0 + 8;
#pragma unroll
    for (int dt = 0; dt < 8; dt++) {
        int e = h * HDIM + dt * 8 + 2 * t;
        *reinterpret_cast<uint32_t*>(&g_cf[(size_t)(b * SEQ + r0) * EMBED + e]) =
            pk2h(o[dt][0] * inv0, o[dt][1] * inv0);
        *reinterpret_cast<uint32_t*>(&g_cf[(size_t)(b * SEQ + r1) * EMBED + e]) =
            pk2h(o[dt][2] * inv1, o[dt][3] * inv1);
    }
}

// ---------------------------------------------------------------------------
extern "C" void kernel_launch(void* const* d_in, const int* in_sizes, int n_in,
                              void* d_out, int out_size)
{
    const float* x    = (const float*)d_in[0];
    const int*   mask = (const int*)d_in[1];
    const float* Wq   = (const float*)d_in[2];
    const float* bq   = (const float*)d_in[3];
    const float* Wk   = (const float*)d_in[4];
    const float* bk   = (const float*)d_in[5];
    const float* Wv   = (const float*)d_in[6];
    const float* bv   = (const float*)d_in[7];
    const float* Wo   = (const float*)d_in[8];
    const float* bo   = (const float*)d_in[9];
    float* out = (float*)d_out;
    (void)in_sizes; (void)n_in; (void)out_size;

    cudaFuncSetAttribute(qkv_mma_kernel,
                         cudaFuncAttributeMaxDynamicSharedMemorySize, GSMEM2);
    cudaFuncSetAttribute(oproj_mma_kernel,
                         cudaFuncAttributeMaxDynamicSharedMemorySize, GSMEM2);
    cudaFuncSetAttribute(attn_mma_kernel,
                         cudaFuncAttributeMaxDynamicSharedMemorySize, ASMEM2);

    cvt_x_kernel<<<(MROWS * EMBED) / 1024, 256>>>(x);
    cvt_w_kernel<<<dim3(32, 32, 4), dim3(32, 8)>>>(Wq, Wk, Wv, Wo);

    dim3 gq(EMBED / 128, MROWS / 128, 3);   // 768 CTAs
    qkv_mma_kernel<<<gq, GTH, GSMEM2>>>(bq, bk, bv);

    dim3 ga(SEQ / 64, NHEAD, BATCH);        // 1024 CTAs
    attn_mma_kernel<<<ga, ATH, ASMEM2>>>(mask);

    dim3 go(EMBED / 128, MROWS / 128, 1);   // 256 CTAs
    oproj_mma_kernel<<<go, GTH, GSMEM2>>>(bo, out);
}

// round 16
// speedup vs baseline: 1.0859x; 1.0859x over previous
#include <cuda_runtime.h>
#include <cuda_bf16.h>
#include <cuda_fp16.h>
#include <cstdint>

#define EMBED 1024
#define NHEAD 16
#define HDIM  64
#define BATCH 2
#define SEQ   2048
#define MROWS (BATCH*SEQ)   // 4096

// ---------------------------------------------------------------------------
// Device-global scratch — single fp16 everywhere.
// Q pre-scaled by 0.125*log2(e) (base-2 softmax domain).
// ---------------------------------------------------------------------------
__device__ __half g_xf [MROWS*EMBED];                           // x  [m][k]
__device__ __half g_wf [4*EMBED*EMBED];                         // W^T [4][n][k]
__device__ __half g_qf [BATCH*NHEAD*SEQ*HDIM];                  // [b,h,s,d]
__device__ __half g_kf [BATCH*NHEAD*SEQ*HDIM];                  // [b,h,s,d]
__device__ __half g_vf [BATCH*NHEAD*HDIM*SEQ];                  // [b,h,d,s]
__device__ __half g_cf [MROWS*EMBED];                           // ctx [m][e]

// ---------------------------------------------------------------------------
// Helpers
// ---------------------------------------------------------------------------
__device__ __forceinline__ uint32_t smem_u32(const void* p) {
    uint32_t a;
    asm("{ .reg .u64 t; cvta.to.shared.u64 t, %1; cvt.u32.u64 %0, t; }"
        : "=r"(a) : "l"(p));
    return a;
}
__device__ __forceinline__ uint32_t pk2h(float e0, float e1) {  // f16x2, e0 low
    uint32_t d;
    asm("cvt.rn.f16x2.f32 %0, %1, %2;" : "=r"(d) : "f"(e1), "f"(e0));
    return d;
}
__device__ __forceinline__ float ex2(float x) {
    float r;
    asm("ex2.approx.f32 %0, %1;" : "=f"(r) : "f"(x));
    return r;
}
__device__ __forceinline__ uint32_t ex2h2(uint32_t x) {         // 2x fp16 exp2
    uint32_t d;
    asm("ex2.approx.f16x2 %0, %1;" : "=r"(d) : "r"(x));
    return d;
}

#define MMAF16(c, a, b0, b1)                                                \
    asm("mma.sync.aligned.m16n8k16.row.col.f32.f16.f16.f32 "                \
        "{%0,%1,%2,%3}, {%4,%5,%6,%7}, {%8,%9}, {%0,%1,%2,%3};"             \
        : "+f"((c)[0]), "+f"((c)[1]), "+f"((c)[2]), "+f"((c)[3])            \
        : "r"((a)[0]), "r"((a)[1]), "r"((a)[2]), "r"((a)[3]),               \
          "r"(b0), "r"(b1))

#define CP_ASYNC16(dst, src)                                                \
    asm volatile("cp.async.cg.shared.global [%0], [%1], 16;"                \
        :: "r"(dst), "l"(src) : "memory")
#define CP_COMMIT() asm volatile("cp.async.commit_group;" ::: "memory")
#define CP_WAIT(n)  asm volatile("cp.async.wait_group %0;" :: "n"(n) : "memory")

#define QSCALE 0.180336880111120419f   // 0.125 * log2(e)

// ---------------------------------------------------------------------------
// Conversion kernels
// ---------------------------------------------------------------------------
extern "C" __global__ void __launch_bounds__(256)
cvt_x_kernel(const float* __restrict__ src)
{
    int i = (blockIdx.x * 256 + threadIdx.x) * 4;
    float4 v = *reinterpret_cast<const float4*>(src + i);
    *reinterpret_cast<uint2*>(g_xf + i) =
        make_uint2(pk2h(v.x, v.y), pk2h(v.z, v.w));
}

extern "C" __global__ void __launch_bounds__(256)
cvt_w_kernel(const float* __restrict__ Wq, const float* __restrict__ Wk,
             const float* __restrict__ Wv, const float* __restrict__ Wo)
{
    __shared__ float t[32][33];
    const float* W = (blockIdx.z == 0) ? Wq : (blockIdx.z == 1) ? Wk :
                     (blockIdx.z == 2) ? Wv : Wo;
    __half* of = g_wf + (size_t)blockIdx.z * EMBED * EMBED;
    int bx = blockIdx.x * 32;  // n base
    int by = blockIdx.y * 32;  // k base
    int tx = threadIdx.x, ty = threadIdx.y;
#pragma unroll
    for (int i = 0; i < 4; i++) {
        int r = ty + i * 8;
        t[r][tx] = W[(size_t)(by + r) * EMBED + bx + tx];
    }
    __syncthreads();
#pragma unroll
    for (int i = 0; i < 4; i++) {
        int r = ty + i * 8;
        of[(size_t)(bx + r) * EMBED + by + tx] = __float2half_rn(t[tx][r]);
    }
}

// ---------------------------------------------------------------------------
// fp16 GEMM (projections): 128x128 tile, 128 threads (2x2 warps), 2 CTAs/SM.
// NEW: 3-stage cp.async pipeline, ONE __syncthreads per iteration.
// Per-output accumulation order identical to R14 -> bit-identical result.
// ---------------------------------------------------------------------------
#define GTH 128
#define GWT (128*36)
#define GBUF (2*GWT)                     // 9216 words per buffer
#define GNBUF 3
#define GSMEM2 (GNBUF*GBUF*4)            // 110592 B (x2 CTAs = 221184)

__device__ __forceinline__ void gemm_stage(
    uint32_t swb, int buf, int tid,
    const __half* sA, const __half* sB, int k0)
{
    const uint32_t dbase = swb + (uint32_t)(buf * GBUF) * 4;
#pragma unroll
    for (int j = 0; j < 8; j++) {
        int idx = tid + j * GTH;
        int r = idx >> 3, c = idx & 7;
        uint32_t doff = (uint32_t)(r * 36 + c * 4) * 4;
        CP_ASYNC16(dbase + doff, sA + (size_t)r * EMBED + k0 + c * 8);
    }
#pragma unroll
    for (int j = 0; j < 8; j++) {
        int idx = tid + j * GTH;
        int r = idx >> 3, c = idx & 7;
        uint32_t doff = (uint32_t)(GWT + r * 36 + c * 4) * 4;
        CP_ASYNC16(dbase + doff, sB + (size_t)r * EMBED + k0 + c * 8);
    }
}

__device__ __forceinline__ void gemm_mma_body(
    const __half* __restrict__ A, const __half* __restrict__ B,
    const float* __restrict__ bias, int mode, float* __restrict__ outf, float scale)
{
    extern __shared__ uint32_t sw[];
    const uint32_t swb = smem_u32(sw);
    const int tid = threadIdx.x;
    const int lane = tid & 31, wid = tid >> 5;
    const int g = lane >> 2, t = lane & 3;
    const int wm = wid & 1, wn = wid >> 1;
    const int m0 = blockIdx.y * 128, n0 = blockIdx.x * 128;

    const __half* sA = A + (size_t)m0 * EMBED;
    const __half* sB = B + (size_t)n0 * EMBED;

    float acc[4][8][4];
#pragma unroll
    for (int a = 0; a < 4; a++)
#pragma unroll
        for (int b = 0; b < 8; b++)
#pragma unroll
            for (int c = 0; c < 4; c++) acc[a][b][c] = 0.f;

    // prologue: prefetch tiles 0 and 1
    gemm_stage(swb, 0, tid, sA, sB, 0);
    CP_COMMIT();
    gemm_stage(swb, 1, tid, sA, sB, 64);
    CP_COMMIT();

    for (int it = 0; it < 16; it++) {
        const int buf = it % 3;
        CP_WAIT(1);        // tile `it` landed (tile it+1 may be in flight)
        __syncthreads();   // all warps done with buf (it-1)%3; tile it visible

        uint32_t* As = sw + buf * GBUF;
        uint32_t* Bs = As + GWT;

#pragma unroll
        for (int ks = 0; ks < 4; ks++) {
            uint32_t ah[4][4];
#pragma unroll
            for (int mt = 0; mt < 4; mt++) {
                int r = wm * 64 + mt * 16 + g;
                int base = r * 36 + ks * 8 + t;
                ah[mt][0] = As[base];     ah[mt][1] = As[base + 8*36];
                ah[mt][2] = As[base + 4]; ah[mt][3] = As[base + 8*36 + 4];
            }
#pragma unroll
            for (int ntp = 0; ntp < 4; ntp++) {
                uint32_t b0[2], b1[2];
#pragma unroll
                for (int q = 0; q < 2; q++) {
                    int n = wn * 64 + (2 * ntp + q) * 8 + g;
                    int base = n * 36 + ks * 8 + t;
                    b0[q] = Bs[base]; b1[q] = Bs[base + 4];
                }
#pragma unroll
                for (int q = 0; q < 2; q++)
#pragma unroll
                    for (int mt = 0; mt < 4; mt++)
                        MMAF16(acc[mt][2*ntp+q], ah[mt], b0[q], b1[q]);
            }
        }

        // prefetch tile it+2 (empty commit keeps group accounting uniform)
        if (it + 2 < 16)
            gemm_stage(swb, (it + 2) % 3, tid, sA, sB, (it + 2) * 64);
        CP_COMMIT();
    }

    // epilogue
#pragma unroll
    for (int mt = 0; mt < 4; mt++) {
#pragma unroll
        for (int nt = 0; nt < 8; nt++) {
            int r0 = m0 + wm * 64 + mt * 16 + g;
            int r1 = r0 + 8;
            int c0 = n0 + wn * 64 + nt * 8 + 2 * t;
            float2 bb = *reinterpret_cast<const float2*>(&bias[c0]);
            float v0 = (acc[mt][nt][0] + bb.x) * scale;
            float v1 = (acc[mt][nt][1] + bb.y) * scale;
            float v2 = (acc[mt][nt][2] + bb.x) * scale;
            float v3 = (acc[mt][nt][3] + bb.y) * scale;
            if (mode == 0) {
                *reinterpret_cast<float2*>(&outf[(size_t)r0 * EMBED + c0]) = make_float2(v0, v1);
                *reinterpret_cast<float2*>(&outf[(size_t)r1 * EMBED + c0]) = make_float2(v2, v3);
            } else {
                int hh = c0 >> 6, d = c0 & 63;
                int b0i = r0 >> 11, s0i = r0 & (SEQ - 1);
                int b1i = r1 >> 11, s1i = r1 & (SEQ - 1);
                if (mode <= 2) {
                    __half* dst = (mode == 1) ? g_qf : g_kf;
                    size_t o0 = ((size_t)(b0i*NHEAD+hh)*SEQ + s0i)*HDIM + d;
                    size_t o1 = ((size_t)(b1i*NHEAD+hh)*SEQ + s1i)*HDIM + d;
                    *reinterpret_cast<uint32_t*>(dst + o0) = pk2h(v0, v1);
                    *reinterpret_cast<uint32_t*>(dst + o1) = pk2h(v2, v3);
                } else {
                    size_t base0 = (size_t)(b0i*NHEAD+hh)*HDIM*SEQ;
                    size_t base1 = (size_t)(b1i*NHEAD+hh)*HDIM*SEQ;
                    g_vf[base0 + (size_t)d * SEQ + s0i]     = __float2half_rn(v0);
                    g_vf[base0 + (size_t)(d+1) * SEQ + s0i] = __float2half_rn(v1);
                    g_vf[base1 + (size_t)d * SEQ + s1i]     = __float2half_rn(v2);
                    g_vf[base1 + (size_t)(d+1) * SEQ + s1i] = __float2half_rn(v3);
                }
            }
        }
    }
}

extern "C" __global__ void __launch_bounds__(GTH, 2)
qkv_mma_kernel(const float* __restrict__ bq, const float* __restrict__ bk,
               const float* __restrict__ bv)
{
    const int z = blockIdx.z;
    const __half* B = g_wf + (size_t)z * EMBED * EMBED;
    const float* bias = (z == 0) ? bq : (z == 1) ? bk : bv;
    int mode = (z == 0) ? 1 : (z == 1) ? 2 : 3;
    float scale = (z == 0) ? QSCALE : 1.0f;
    gemm_mma_body(g_xf, B, bias, mode, nullptr, scale);
}

extern "C" __global__ void __launch_bounds__(GTH, 2)
oproj_mma_kernel(const float* __restrict__ bo, float* __restrict__ out)
{
    gemm_mma_body(g_cf, g_wf + (size_t)3 * EMBED * EMBED, bo, 0, out, 1.0f);
}

// ---------------------------------------------------------------------------
// Flash attention — EXACT R14 champion (128-thread CTAs, 2/SM, q-tile 64,
// smem mask, ph-hoist, register fragment prefetch, NBUF=2).
// ---------------------------------------------------------------------------
#define ATH 128
#define KW (128*36)
#define VW2 (72*68)
#define ABUFW (KW + VW2)
#define ASMEM2 ((2*ABUFW + SEQ)*4)       // 84224 B

__device__ __forceinline__ void attn_stage_kv(
    uint32_t swb, int buf, int tid,
    const __half* kf, const __half* vf, int s0)
{
    const uint32_t dbase = swb + (uint32_t)(buf * ABUFW) * 4;
#pragma unroll
    for (int j = 0; j < 8; j++) {
        int idx = tid + j * ATH;
        {
            int r = idx >> 3, c = idx & 7;
            uint32_t doff = (uint32_t)(r * 36 + c * 4) * 4;
            CP_ASYNC16(dbase + doff, kf + (size_t)(s0 + r) * HDIM + c * 8);
        }
        {
            int d = idx >> 4, c = idx & 15;
            uint32_t doff = (uint32_t)(KW + d * 68 + c * 4) * 4;
            CP_ASYNC16(dbase + doff, vf + (size_t)d * SEQ + s0 + c * 8);
        }
    }
}

extern "C" __global__ void __launch_bounds__(ATH, 2)
attn_mma_kernel(const int* __restrict__ mask)
{
    extern __shared__ uint32_t sw[];
    const uint32_t swb = smem_u32(sw);
    float* mskf = reinterpret_cast<float*>(sw + 2 * ABUFW);

    const int tid = threadIdx.x, lane = tid & 31, wid = tid >> 5;
    const int g = lane >> 2, t = lane & 3;
    const int b = blockIdx.z, h = blockIdx.y;
    const int q0 = blockIdx.x * 64;
    const int qw = wid * 16;
    const size_t bh = (size_t)(b * NHEAD + h);
    const __half* qfp = g_qf + bh * SEQ * HDIM;
    const __half* kfp = g_kf + bh * SEQ * HDIM;
    const __half* vfp = g_vf + bh * HDIM * SEQ;
    const int* mb = mask + b * SEQ;

#pragma unroll
    for (int i = 0; i < SEQ / ATH; i++)
        mskf[tid + i * ATH] = (float)mb[tid + i * ATH];

    for (int i = tid; i < 2 * 8 * 68; i += ATH) {
        int bufi = i / (8 * 68);
        int rr = (i / 68) % 8;
        int cc = i % 68;
        sw[bufi * ABUFW + KW + (64 + rr) * 68 + cc] =
            (rr == 0) ? 0x3C003C00u : 0u;
    }

#pragma unroll
    for (int j = 0; j < 4; j++) {
        int idx = tid + j * ATH;
        int r = idx >> 3, c = idx & 7;
        uint32_t doff = (uint32_t)(r * 36 + c * 4) * 4;
        CP_ASYNC16(swb + doff, qfp + (size_t)(q0 + r) * HDIM + c * 8);
    }
    CP_COMMIT();
    CP_WAIT(0);
    __syncthreads();

    uint32_t qh[4][4];
#pragma unroll
    for (int ks = 0; ks < 4; ks++) {
#pragma unroll
        for (int p = 0; p < 4; p++) {
            int row = qw + g + ((p & 1) ? 8 : 0);
            int col = ks * 8 + t + ((p >= 2) ? 4 : 0);
            qh[ks][p] = sw[row * 36 + col];
        }
    }
    __syncthreads();

    attn_stage_kv(swb, 0, tid, kfp, vfp, 0);
    CP_COMMIT();

    float mrow[2] = {-1e30f, -1e30f};
    float o[8][4], ol[4];
#pragma unroll
    for (int i = 0; i < 8; i++)
#pragma unroll
        for (int j = 0; j < 4; j++) o[i][j] = 0.f;
#pragma unroll
    for (int j = 0; j < 4; j++) ol[j] = 0.f;

    for (int it = 0; it < 16; it++) {
        const int buf = it & 1;
        const int s0 = it * 128;
        __syncthreads();
        if (it + 1 < 16) {
            attn_stage_kv(swb, buf ^ 1, tid, kfp, vfp, (it + 1) * 128);
            CP_COMMIT();
            CP_WAIT(1);
        } else {
            CP_WAIT(0);
        }
        __syncthreads();

        uint32_t* Ksh = sw + buf * ABUFW;
        uint32_t* Vth = Ksh + KW;

        float sc[16][4];
#pragma unroll
        for (int nt = 0; nt < 16; nt++)
#pragma unroll
            for (int j = 0; j < 4; j++) sc[nt][j] = 0.f;
        {
            uint32_t kb0[2][4], kb1[2][4];
#pragma unroll
            for (int q = 0; q < 4; q++) {
                int base = (q * 8 + g) * 36 + t;
                kb0[0][q] = Ksh[base]; kb1[0][q] = Ksh[base + 4];
            }
#pragma unroll
            for (int idx = 0; idx < 16; idx++) {
                const int cur = idx & 1;
                if (idx + 1 < 16) {
                    int ks1 = (idx + 1) >> 2, ng1 = (idx + 1) & 3;
#pragma unroll
                    for (int q = 0; q < 4; q++) {
                        int base = ((ng1 * 4 + q) * 8 + g) * 36 + ks1 * 8 + t;
                        kb0[cur ^ 1][q] = Ksh[base];
                        kb1[cur ^ 1][q] = Ksh[base + 4];
                    }
                }
                int ks = idx >> 2, ng = idx & 3;
#pragma unroll
                for (int q = 0; q < 4; q++)
                    MMAF16(sc[ng * 4 + q], qh[ks], kb0[cur][q], kb1[cur][q]);
            }
        }

#pragma unroll
        for (int nt = 0; nt < 16; nt++) {
            float2 mv = *reinterpret_cast<float2*>(&mskf[s0 + nt * 8 + 2 * t]);
            if (mv.x == 0.f) { sc[nt][0] = -1e30f; sc[nt][2] = -1e30f; }
            if (mv.y == 0.f) { sc[nt][1] = -1e30f; sc[nt][3] = -1e30f; }
        }

        float alpha[2];
#pragma unroll
        for (int rh = 0; rh < 2; rh++) {
            float mt_ = -1e30f;
#pragma unroll
            for (int nt = 0; nt < 16; nt++)
                mt_ = fmaxf(mt_, fmaxf(sc[nt][rh * 2 + 0], sc[nt][rh * 2 + 1]));
            mt_ = fmaxf(mt_, __shfl_xor_sync(0xffffffffu, mt_, 1));
            mt_ = fmaxf(mt_, __shfl_xor_sync(0xffffffffu, mt_, 2));
            float mn = fmaxf(mrow[rh], mt_);
            alpha[rh] = ex2(mrow[rh] - mn);
            mrow[rh] = mn;
        }
#pragma unroll
        for (int dt = 0; dt < 8; dt++) {
            o[dt][0] *= alpha[0]; o[dt][1] *= alpha[0];
            o[dt][2] *= alpha[1]; o[dt][3] *= alpha[1];
        }
        ol[0] *= alpha[0]; ol[1] *= alpha[0];
        ol[2] *= alpha[1]; ol[3] *= alpha[1];

        uint32_t ph[8][4];
#pragma unroll
        for (int j = 0; j < 8; j++)
#pragma unroll
            for (int p = 0; p < 4; p++) {
                int nt = 2 * j + (p >> 1);
                int rh = p & 1;
                int ix = rh * 2;
                ph[j][p] = ex2h2(pk2h(sc[nt][ix]     - mrow[rh],
                                      sc[nt][ix + 1] - mrow[rh]));
            }

        {
            uint32_t vb0[2][4], vb1[2][4];
#pragma unroll
            for (int q = 0; q < 4; q++) {
                int base = (q * 8 + g) * 68 + t;
                vb0[0][q] = Vth[base]; vb1[0][q] = Vth[base + 4];
            }
#pragma unroll
            for (int idx = 0; idx < 16; idx++) {
                const int cur = idx & 1;
                if (idx + 1 < 16) {
                    int j1 = (idx + 1) >> 1, dg1 = (idx + 1) & 1;
#pragma unroll
                    for (int q = 0; q < 4; q++) {
                        int base = ((dg1 * 4 + q) * 8 + g) * 68 + j1 * 8 + t;
                        vb0[cur ^ 1][q] = Vth[base];
                        vb1[cur ^ 1][q] = Vth[base + 4];
                    }
                }
                int j = idx >> 1, dg = idx & 1;
#pragma unroll
                for (int q = 0; q < 4; q++)
                    MMAF16(o[dg * 4 + q], ph[j], vb0[cur][q], vb1[cur][q]);
            }
        }
#pragma unroll
        for (int j = 0; j < 8; j++) {
            int base = (64 + g) * 68 + j * 8 + t;
            MMAF16(ol, ph[j], Vth[base], Vth[base + 4]);
        }
    }

    float l0 = __shfl_sync(0xffffffffu, ol[0], lane & 28);
    float l1 = __shfl_sync(0xffffffffu, ol[2], lane & 28);
    float inv0 = (l0 > 0.f) ? (1.f / l0) : 0.f;
    float inv1 = (l1 > 0.f) ? (1.f / l1) : 0.f;
    int r0 = q0 + qw + g, r1 = r0 + 8;
#pragma unroll
    for (int dt = 0; dt < 8; dt++) {
        int e = h * HDIM + dt * 8 + 2 * t;
        *reinterpret_cast<uint32_t*>(&g_cf[(size_t)(b * SEQ + r0) * EMBED + e]) =
            pk2h(o[dt][0] * inv0, o[dt][1] * inv0);
        *reinterpret_cast<uint32_t*>(&g_cf[(size_t)(b * SEQ + r1) * EMBED + e]) =
            pk2h(o[dt][2] * inv1, o[dt][3] * inv1);
    }
}

// ---------------------------------------------------------------------------
extern "C" void kernel_launch(void* const* d_in, const int* in_sizes, int n_in,
                              void* d_out, int out_size)
{
    const float* x    = (const float*)d_in[0];
    const int*   mask = (const int*)d_in[1];
    const float* Wq   = (const float*)d_in[2];
    const float* bq   = (const float*)d_in[3];
    const float* Wk   = (const float*)d_in[4];
    const float* bk   = (const float*)d_in[5];
    const float* Wv   = (const float*)d_in[6];
    const float* bv   = (const float*)d_in[7];
    const float* Wo   = (const float*)d_in[8];
    const float* bo   = (const float*)d_in[9];
    float* out = (float*)d_out;
    (void)in_sizes; (void)n_in; (void)out_size;

    cudaFuncSetAttribute(qkv_mma_kernel,
                         cudaFuncAttributeMaxDynamicSharedMemorySize, GSMEM2);
    cudaFuncSetAttribute(oproj_mma_kernel,
                         cudaFuncAttributeMaxDynamicSharedMemorySize, GSMEM2);
    cudaFuncSetAttribute(attn_mma_kernel,
                         cudaFuncAttributeMaxDynamicSharedMemorySize, ASMEM2);

    cvt_x_kernel<<<(MROWS * EMBED) / 1024, 256>>>(x);
    cvt_w_kernel<<<dim3(32, 32, 4), dim3(32, 8)>>>(Wq, Wk, Wv, Wo);

    dim3 gq(EMBED / 128, MROWS / 128, 3);   // 768 CTAs
    qkv_mma_kernel<<<gq, GTH, GSMEM2>>>(bq, bk, bv);

    dim3 ga(SEQ / 64, NHEAD, BATCH);        // 1024 CTAs
    attn_mma_kernel<<<ga, ATH, ASMEM2>>>(mask);

    dim3 go(EMBED / 128, MROWS / 128, 1);   // 256 CTAs
    oproj_mma_kernel<<<go, GTH, GSMEM2>>>(bo, out);
}

// round 17
// speedup vs baseline: 1.2882x; 1.1863x over previous
#include <cuda_runtime.h>
#include <cuda_bf16.h>
#include <cuda_fp16.h>
#include <cstdint>

#define EMBED 1024
#define NHEAD 16
#define HDIM  64
#define BATCH 2
#define SEQ   2048
#define MROWS (BATCH*SEQ)   // 4096

// ---------------------------------------------------------------------------
// Device-global scratch — single fp16. Q pre-scaled by 0.125*log2(e).
// K/V are stored COMPACTED (masked key positions removed, per batch).
// ---------------------------------------------------------------------------
__device__ __half g_xf [MROWS*EMBED];
__device__ __half g_wf [4*EMBED*EMBED];
__device__ __half g_qf [BATCH*NHEAD*SEQ*HDIM];    // [b,h,s,d] (full)
__device__ __half g_kf [BATCH*NHEAD*SEQ*HDIM];    // [b,h,s',d] compacted
__device__ __half g_vf [BATCH*NHEAD*HDIM*SEQ];    // [b,h,d,s'] compacted
__device__ __half g_cf [MROWS*EMBED];
__device__ int    g_cpos[BATCH*SEQ];              // exclusive prefix of mask
__device__ int    g_nkeep[BATCH];                 // kept keys per batch

// ---------------------------------------------------------------------------
// Helpers
// ---------------------------------------------------------------------------
__device__ __forceinline__ uint32_t smem_u32(const void* p) {
    uint32_t a;
    asm("{ .reg .u64 t; cvta.to.shared.u64 t, %1; cvt.u32.u64 %0, t; }"
        : "=r"(a) : "l"(p));
    return a;
}
__device__ __forceinline__ uint32_t pk2h(float e0, float e1) {
    uint32_t d;
    asm("cvt.rn.f16x2.f32 %0, %1, %2;" : "=r"(d) : "f"(e1), "f"(e0));
    return d;
}
__device__ __forceinline__ float ex2(float x) {
    float r;
    asm("ex2.approx.f32 %0, %1;" : "=f"(r) : "f"(x));
    return r;
}
__device__ __forceinline__ uint32_t ex2h2(uint32_t x) {
    uint32_t d;
    asm("ex2.approx.f16x2 %0, %1;" : "=r"(d) : "r"(x));
    return d;
}

#define MMAF16(c, a, b0, b1)                                                \
    asm("mma.sync.aligned.m16n8k16.row.col.f32.f16.f16.f32 "                \
        "{%0,%1,%2,%3}, {%4,%5,%6,%7}, {%8,%9}, {%0,%1,%2,%3};"             \
        : "+f"((c)[0]), "+f"((c)[1]), "+f"((c)[2]), "+f"((c)[3])            \
        : "r"((a)[0]), "r"((a)[1]), "r"((a)[2]), "r"((a)[3]),               \
          "r"(b0), "r"(b1))

#define CP_ASYNC16(dst, src)                                                \
    asm volatile("cp.async.cg.shared.global [%0], [%1], 16;"                \
        :: "r"(dst), "l"(src) : "memory")
#define CP_COMMIT() asm volatile("cp.async.commit_group;" ::: "memory")
#define CP_WAIT(n)  asm volatile("cp.async.wait_group %0;" :: "n"(n) : "memory")

#define QSCALE 0.180336880111120419f   // 0.125 * log2(e)

// ---------------------------------------------------------------------------
// mask scan: per batch, exclusive prefix + total (block scan, 256 thr x 8 elem)
// ---------------------------------------------------------------------------
extern "C" __global__ void __launch_bounds__(256)
mask_scan_kernel(const int* __restrict__ mask)
{
    __shared__ int ssum[256];
    const int b = blockIdx.x;
    const int* mb = mask + b * SEQ;
    const int tid = threadIdx.x;
    int loc[8], s = 0;
#pragma unroll
    for (int i = 0; i < 8; i++) { loc[i] = mb[tid * 8 + i]; s += loc[i]; }
    ssum[tid] = s;
    __syncthreads();
    for (int off = 1; off < 256; off <<= 1) {
        int v = (tid >= off) ? ssum[tid - off] : 0;
        __syncthreads();
        ssum[tid] += v;
        __syncthreads();
    }
    int run = (tid == 0) ? 0 : ssum[tid - 1];
#pragma unroll
    for (int i = 0; i < 8; i++) { g_cpos[b * SEQ + tid * 8 + i] = run; run += loc[i]; }
    if (tid == 255) g_nkeep[b] = run;
}

// ---------------------------------------------------------------------------
// Conversion kernels
// ---------------------------------------------------------------------------
extern "C" __global__ void __launch_bounds__(256)
cvt_x_kernel(const float* __restrict__ src)
{
    int i = (blockIdx.x * 256 + threadIdx.x) * 4;
    float4 v = *reinterpret_cast<const float4*>(src + i);
    *reinterpret_cast<uint2*>(g_xf + i) =
        make_uint2(pk2h(v.x, v.y), pk2h(v.z, v.w));
}

extern "C" __global__ void __launch_bounds__(256)
cvt_w_kernel(const float* __restrict__ Wq, const float* __restrict__ Wk,
             const float* __restrict__ Wv, const float* __restrict__ Wo)
{
    __shared__ float t[32][33];
    const float* W = (blockIdx.z == 0) ? Wq : (blockIdx.z == 1) ? Wk :
                     (blockIdx.z == 2) ? Wv : Wo;
    __half* of = g_wf + (size_t)blockIdx.z * EMBED * EMBED;
    int bx = blockIdx.x * 32;
    int by = blockIdx.y * 32;
    int tx = threadIdx.x, ty = threadIdx.y;
#pragma unroll
    for (int i = 0; i < 4; i++) {
        int r = ty + i * 8;
        t[r][tx] = W[(size_t)(by + r) * EMBED + bx + tx];
    }
    __syncthreads();
#pragma unroll
    for (int i = 0; i < 4; i++) {
        int r = ty + i * 8;
        of[(size_t)(bx + r) * EMBED + by + tx] = __float2half_rn(t[tx][r]);
    }
}

// ---------------------------------------------------------------------------
// fp16 GEMM (projections): 128x128 tile, 128 thr (2x2 warps), 2 CTAs/SM,
// 3-stage cp.async pipeline, one sync/iter (R16 champion).
// modes: 0 fp32 out; 1 Q (full, QSCALE); 2 K (compacted); 3 Vt (compacted).
// ---------------------------------------------------------------------------
#define GTH 128
#define GWT (128*36)
#define GBUF (2*GWT)
#define GNBUF 3
#define GSMEM2 (GNBUF*GBUF*4)            // 110592 B

__device__ __forceinline__ void gemm_stage(
    uint32_t swb, int buf, int tid,
    const __half* sA, const __half* sB, int k0)
{
    const uint32_t dbase = swb + (uint32_t)(buf * GBUF) * 4;
#pragma unroll
    for (int j = 0; j < 8; j++) {
        int idx = tid + j * GTH;
        int r = idx >> 3, c = idx & 7;
        uint32_t doff = (uint32_t)(r * 36 + c * 4) * 4;
        CP_ASYNC16(dbase + doff, sA + (size_t)r * EMBED + k0 + c * 8);
    }
#pragma unroll
    for (int j = 0; j < 8; j++) {
        int idx = tid + j * GTH;
        int r = idx >> 3, c = idx & 7;
        uint32_t doff = (uint32_t)(GWT + r * 36 + c * 4) * 4;
        CP_ASYNC16(dbase + doff, sB + (size_t)r * EMBED + k0 + c * 8);
    }
}

__device__ __forceinline__ void gemm_mma_body(
    const __half* __restrict__ A, const __half* __restrict__ B,
    const float* __restrict__ bias, int mode, float* __restrict__ outf,
    float scale, const int* __restrict__ maskp)
{
    extern __shared__ uint32_t sw[];
    const uint32_t swb = smem_u32(sw);
    const int tid = threadIdx.x;
    const int lane = tid & 31, wid = tid >> 5;
    const int g = lane >> 2, t = lane & 3;
    const int wm = wid & 1, wn = wid >> 1;
    const int m0 = blockIdx.y * 128, n0 = blockIdx.x * 128;

    const __half* sA = A + (size_t)m0 * EMBED;
    const __half* sB = B + (size_t)n0 * EMBED;

    float acc[4][8][4];
#pragma unroll
    for (int a = 0; a < 4; a++)
#pragma unroll
        for (int b = 0; b < 8; b++)
#pragma unroll
            for (int c = 0; c < 4; c++) acc[a][b][c] = 0.f;

    gemm_stage(swb, 0, tid, sA, sB, 0);
    CP_COMMIT();
    gemm_stage(swb, 1, tid, sA, sB, 64);
    CP_COMMIT();

    for (int it = 0; it < 16; it++) {
        const int buf = it % 3;
        CP_WAIT(1);
        __syncthreads();

        uint32_t* As = sw + buf * GBUF;
        uint32_t* Bs = As + GWT;

#pragma unroll
        for (int ks = 0; ks < 4; ks++) {
            uint32_t ah[4][4];
#pragma unroll
            for (int mt = 0; mt < 4; mt++) {
                int r = wm * 64 + mt * 16 + g;
                int base = r * 36 + ks * 8 + t;
                ah[mt][0] = As[base];     ah[mt][1] = As[base + 8*36];
                ah[mt][2] = As[base + 4]; ah[mt][3] = As[base + 8*36 + 4];
            }
#pragma unroll
            for (int ntp = 0; ntp < 4; ntp++) {
                uint32_t b0[2], b1[2];
#pragma unroll
                for (int q = 0; q < 2; q++) {
                    int n = wn * 64 + (2 * ntp + q) * 8 + g;
                    int base = n * 36 + ks * 8 + t;
                    b0[q] = Bs[base]; b1[q] = Bs[base + 4];
                }
#pragma unroll
                for (int q = 0; q < 2; q++)
#pragma unroll
                    for (int mt = 0; mt < 4; mt++)
                        MMAF16(acc[mt][2*ntp+q], ah[mt], b0[q], b1[q]);
            }
        }

        if (it + 2 < 16)
            gemm_stage(swb, (it + 2) % 3, tid, sA, sB, (it + 2) * 64);
        CP_COMMIT();
    }

    // epilogue
#pragma unroll
    for (int mt = 0; mt < 4; mt++) {
        int r0 = m0 + wm * 64 + mt * 16 + g;
        int r1 = r0 + 8;
        int b0i = r0 >> 11, s0i = r0 & (SEQ - 1);
        int b1i = r1 >> 11, s1i = r1 & (SEQ - 1);
        int k0v = 1, k1v = 1, p0 = s0i, p1 = s1i;
        if (mode >= 2) {                 // compaction info for K/V
            k0v = maskp[b0i * SEQ + s0i];
            k1v = maskp[b1i * SEQ + s1i];
            p0  = g_cpos[b0i * SEQ + s0i];
            p1  = g_cpos[b1i * SEQ + s1i];
        }
#pragma unroll
        for (int nt = 0; nt < 8; nt++) {
            int c0 = n0 + wn * 64 + nt * 8 + 2 * t;
            float2 bb = *reinterpret_cast<const float2*>(&bias[c0]);
            float v0 = (acc[mt][nt][0] + bb.x) * scale;
            float v1 = (acc[mt][nt][1] + bb.y) * scale;
            float v2 = (acc[mt][nt][2] + bb.x) * scale;
            float v3 = (acc[mt][nt][3] + bb.y) * scale;
            if (mode == 0) {
                *reinterpret_cast<float2*>(&outf[(size_t)r0 * EMBED + c0]) = make_float2(v0, v1);
                *reinterpret_cast<float2*>(&outf[(size_t)r1 * EMBED + c0]) = make_float2(v2, v3);
            } else {
                int hh = c0 >> 6, d = c0 & 63;
                if (mode == 1) {          // Q: full layout
                    size_t o0 = ((size_t)(b0i*NHEAD+hh)*SEQ + s0i)*HDIM + d;
                    size_t o1 = ((size_t)(b1i*NHEAD+hh)*SEQ + s1i)*HDIM + d;
                    *reinterpret_cast<uint32_t*>(g_qf + o0) = pk2h(v0, v1);
                    *reinterpret_cast<uint32_t*>(g_qf + o1) = pk2h(v2, v3);
                } else if (mode == 2) {   // K: compacted rows
                    if (k0v) {
                        size_t o0 = ((size_t)(b0i*NHEAD+hh)*SEQ + p0)*HDIM + d;
                        *reinterpret_cast<uint32_t*>(g_kf + o0) = pk2h(v0, v1);
                    }
                    if (k1v) {
                        size_t o1 = ((size_t)(b1i*NHEAD+hh)*SEQ + p1)*HDIM + d;
                        *reinterpret_cast<uint32_t*>(g_kf + o1) = pk2h(v2, v3);
                    }
                } else {                  // Vt: compacted columns
                    if (k0v) {
                        size_t base0 = (size_t)(b0i*NHEAD+hh)*HDIM*SEQ;
                        g_vf[base0 + (size_t)d * SEQ + p0]       = __float2half_rn(v0);
                        g_vf[base0 + (size_t)(d+1) * SEQ + p0]   = __float2half_rn(v1);
                    }
                    if (k1v) {
                        size_t base1 = (size_t)(b1i*NHEAD+hh)*HDIM*SEQ;
                        g_vf[base1 + (size_t)d * SEQ + p1]       = __float2half_rn(v2);
                        g_vf[base1 + (size_t)(d+1) * SEQ + p1]   = __float2half_rn(v3);
                    }
                }
            }
        }
    }
}

extern "C" __global__ void __launch_bounds__(GTH, 2)
qkv_mma_kernel(const float* __restrict__ bq, const float* __restrict__ bk,
               const float* __restrict__ bv, const int* __restrict__ mask)
{
    const int z = blockIdx.z;
    const __half* B = g_wf + (size_t)z * EMBED * EMBED;
    const float* bias = (z == 0) ? bq : (z == 1) ? bk : bv;
    int mode = (z == 0) ? 1 : (z == 1) ? 2 : 3;
    float scale = (z == 0) ? QSCALE : 1.0f;
    gemm_mma_body(g_xf, B, bias, mode, nullptr, scale, mask);
}

extern "C" __global__ void __launch_bounds__(GTH, 2)
oproj_mma_kernel(const float* __restrict__ bo, float* __restrict__ out)
{
    gemm_mma_body(g_cf, g_wf + (size_t)3 * EMBED * EMBED, bo, 0, out, 1.0f, nullptr);
}

// ---------------------------------------------------------------------------
// Flash attention over COMPACTED keys: loop ntiles = ceil(nkeep/128);
// only the last tile masks (index compare). R14 structure otherwise.
// ---------------------------------------------------------------------------
#define ATH 128
#define KW (128*36)
#define VW2 (72*68)
#define ABUFW (KW + VW2)
#define ASMEM2 (2*ABUFW*4)               // 76032 B (mask smem removed)

__device__ __forceinline__ void attn_stage_kv(
    uint32_t swb, int buf, int tid,
    const __half* kf, const __half* vf, int s0)
{
    const uint32_t dbase = swb + (uint32_t)(buf * ABUFW) * 4;
#pragma unroll
    for (int j = 0; j < 8; j++) {
        int idx = tid + j * ATH;
        {
            int r = idx >> 3, c = idx & 7;
            uint32_t doff = (uint32_t)(r * 36 + c * 4) * 4;
            CP_ASYNC16(dbase + doff, kf + (size_t)(s0 + r) * HDIM + c * 8);
        }
        {
            int d = idx >> 4, c = idx & 15;
            uint32_t doff = (uint32_t)(KW + d * 68 + c * 4) * 4;
            CP_ASYNC16(dbase + doff, vf + (size_t)d * SEQ + s0 + c * 8);
        }
    }
}

extern "C" __global__ void __launch_bounds__(ATH, 2)
attn_mma_kernel(const int* __restrict__ mask)
{
    extern __shared__ uint32_t sw[];
    const uint32_t swb = smem_u32(sw);
    (void)mask;

    const int tid = threadIdx.x, lane = tid & 31, wid = tid >> 5;
    const int g = lane >> 2, t = lane & 3;
    const int b = blockIdx.z, h = blockIdx.y;
    const int q0 = blockIdx.x * 64;
    const int qw = wid * 16;
    const size_t bh = (size_t)(b * NHEAD + h);
    const __half* qfp = g_qf + bh * SEQ * HDIM;
    const __half* kfp = g_kf + bh * SEQ * HDIM;
    const __half* vfp = g_vf + bh * HDIM * SEQ;

    const int nk = g_nkeep[b];
    const int ntiles = (nk + 127) >> 7;

    // ones-row (row 64 = 1.0) and zero rows (65..71), both buffers
    for (int i = tid; i < 2 * 8 * 68; i += ATH) {
        int bufi = i / (8 * 68);
        int rr = (i / 68) % 8;
        int cc = i % 68;
        sw[bufi * ABUFW + KW + (64 + rr) * 68 + cc] =
            (rr == 0) ? 0x3C003C00u : 0u;
    }

    // stage Q (64 rows) into buf0 K-area, extract fragments
#pragma unroll
    for (int j = 0; j < 4; j++) {
        int idx = tid + j * ATH;
        int r = idx >> 3, c = idx & 7;
        uint32_t doff = (uint32_t)(r * 36 + c * 4) * 4;
        CP_ASYNC16(swb + doff, qfp + (size_t)(q0 + r) * HDIM + c * 8);
    }
    CP_COMMIT();
    CP_WAIT(0);
    __syncthreads();

    uint32_t qh[4][4];
#pragma unroll
    for (int ks = 0; ks < 4; ks++) {
#pragma unroll
        for (int p = 0; p < 4; p++) {
            int row = qw + g + ((p & 1) ? 8 : 0);
            int col = ks * 8 + t + ((p >= 2) ? 4 : 0);
            qh[ks][p] = sw[row * 36 + col];
        }
    }
    __syncthreads();

    if (ntiles > 0)
        attn_stage_kv(swb, 0, tid, kfp, vfp, 0);
    CP_COMMIT();

    float mrow[2] = {-1e30f, -1e30f};
    float o[8][4], ol[4];
#pragma unroll
    for (int i = 0; i < 8; i++)
#pragma unroll
        for (int j = 0; j < 4; j++) o[i][j] = 0.f;
#pragma unroll
    for (int j = 0; j < 4; j++) ol[j] = 0.f;

    for (int it = 0; it < ntiles; it++) {
        const int buf = it & 1;
        const int s0 = it * 128;
        __syncthreads();
        if (it + 1 < ntiles) {
            attn_stage_kv(swb, buf ^ 1, tid, kfp, vfp, (it + 1) * 128);
            CP_COMMIT();
            CP_WAIT(1);
        } else {
            CP_WAIT(0);
        }
        __syncthreads();

        uint32_t* Ksh = sw + buf * ABUFW;
        uint32_t* Vth = Ksh + KW;

        // ---- S = Q K^T (register-prefetched fragments)
        float sc[16][4];
#pragma unroll
        for (int nt = 0; nt < 16; nt++)
#pragma unroll
            for (int j = 0; j < 4; j++) sc[nt][j] = 0.f;
        {
            uint32_t kb0[2][4], kb1[2][4];
#pragma unroll
            for (int q = 0; q < 4; q++) {
                int base = (q * 8 + g) * 36 + t;
                kb0[0][q] = Ksh[base]; kb1[0][q] = Ksh[base + 4];
            }
#pragma unroll
            for (int idx = 0; idx < 16; idx++) {
                const int cur = idx & 1;
                if (idx + 1 < 16) {
                    int ks1 = (idx + 1) >> 2, ng1 = (idx + 1) & 3;
#pragma unroll
                    for (int q = 0; q < 4; q++) {
                        int base = ((ng1 * 4 + q) * 8 + g) * 36 + ks1 * 8 + t;
                        kb0[cur ^ 1][q] = Ksh[base];
                        kb1[cur ^ 1][q] = Ksh[base + 4];
                    }
                }
                int ks = idx >> 2, ng = idx & 3;
#pragma unroll
                for (int q = 0; q < 4; q++)
                    MMAF16(sc[ng * 4 + q], qh[ks], kb0[cur][q], kb1[cur][q]);
            }
        }

        // ---- tail masking only (all other tiles are fully unmasked)
        if (it == ntiles - 1) {
#pragma unroll
            for (int nt = 0; nt < 16; nt++) {
                int gc = s0 + nt * 8 + 2 * t;
                if (gc >= nk)     { sc[nt][0] = -1e30f; sc[nt][2] = -1e30f; }
                if (gc + 1 >= nk) { sc[nt][1] = -1e30f; sc[nt][3] = -1e30f; }
            }
        }

        // ---- online max + rescale (sum via MMA ones-column)
        float alpha[2];
#pragma unroll
        for (int rh = 0; rh < 2; rh++) {
            float mt_ = -1e30f;
#pragma unroll
            for (int nt = 0; nt < 16; nt++)
                mt_ = fmaxf(mt_, fmaxf(sc[nt][rh * 2 + 0], sc[nt][rh * 2 + 1]));
            mt_ = fmaxf(mt_, __shfl_xor_sync(0xffffffffu, mt_, 1));
            mt_ = fmaxf(mt_, __shfl_xor_sync(0xffffffffu, mt_, 2));
            float mn = fmaxf(mrow[rh], mt_);
            alpha[rh] = ex2(mrow[rh] - mn);
            mrow[rh] = mn;
        }
#pragma unroll
        for (int dt = 0; dt < 8; dt++) {
            o[dt][0] *= alpha[0]; o[dt][1] *= alpha[0];
            o[dt][2] *= alpha[1]; o[dt][3] *= alpha[1];
        }
        ol[0] *= alpha[0]; ol[1] *= alpha[0];
        ol[2] *= alpha[1]; ol[3] *= alpha[1];

        // ---- exp work up front
        uint32_t ph[8][4];
#pragma unroll
        for (int j = 0; j < 8; j++)
#pragma unroll
            for (int p = 0; p < 4; p++) {
                int nt = 2 * j + (p >> 1);
                int rh = p & 1;
                int ix = rh * 2;
                ph[j][p] = ex2h2(pk2h(sc[nt][ix]     - mrow[rh],
                                      sc[nt][ix + 1] - mrow[rh]));
            }

        // ---- O += P V (register-prefetched fragments)
        {
            uint32_t vb0[2][4], vb1[2][4];
#pragma unroll
            for (int q = 0; q < 4; q++) {
                int base = (q * 8 + g) * 68 + t;
                vb0[0][q] = Vth[base]; vb1[0][q] = Vth[base + 4];
            }
#pragma unroll
            for (int idx = 0; idx < 16; idx++) {
                const int cur = idx & 1;
                if (idx + 1 < 16) {
                    int j1 = (idx + 1) >> 1, dg1 = (idx + 1) & 1;
#pragma unroll
                    for (int q = 0; q < 4; q++) {
                        int base = ((dg1 * 4 + q) * 8 + g) * 68 + j1 * 8 + t;
                        vb0[cur ^ 1][q] = Vth[base];
                        vb1[cur ^ 1][q] = Vth[base + 4];
                    }
                }
                int j = idx >> 1, dg = idx & 1;
#pragma unroll
                for (int q = 0; q < 4; q++)
                    MMAF16(o[dg * 4 + q], ph[j], vb0[cur][q], vb1[cur][q]);
            }
        }
#pragma unroll
        for (int j = 0; j < 8; j++) {
            int base = (64 + g) * 68 + j * 8 + t;
            MMAF16(ol, ph[j], Vth[base], Vth[base + 4]);
        }
    }

    // ---- epilogue
    float l0 = __shfl_sync(0xffffffffu, ol[0], lane & 28);
    float l1 = __shfl_sync(0xffffffffu, ol[2], lane & 28);
    float inv0 = (l0 > 0.f) ? (1.f / l0) : 0.f;
    float inv1 = (l1 > 0.f) ? (1.f / l1) : 0.f;
    int r0 = q0 + qw + g, r1 = r0 + 8;
#pragma unroll
    for (int dt = 0; dt < 8; dt++) {
        int e = h * HDIM + dt * 8 + 2 * t;
        *reinterpret_cast<uint32_t*>(&g_cf[(size_t)(b * SEQ + r0) * EMBED + e]) =
            pk2h(o[dt][0] * inv0, o[dt][1] * inv0);
        *reinterpret_cast<uint32_t*>(&g_cf[(size_t)(b * SEQ + r1) * EMBED + e]) =
            pk2h(o[dt][2] * inv1, o[dt][3] * inv1);
    }
}

// ---------------------------------------------------------------------------
extern "C" void kernel_launch(void* const* d_in, const int* in_sizes, int n_in,
                              void* d_out, int out_size)
{
    const float* x    = (const float*)d_in[0];
    const int*   mask = (const int*)d_in[1];
    const float* Wq   = (const float*)d_in[2];
    const float* bq   = (const float*)d_in[3];
    const float* Wk   = (const float*)d_in[4];
    const float* bk   = (const float*)d_in[5];
    const float* Wv   = (const float*)d_in[6];
    const float* bv   = (const float*)d_in[7];
    const float* Wo   = (const float*)d_in[8];
    const float* bo   = (const float*)d_in[9];
    float* out = (float*)d_out;
    (void)in_sizes; (void)n_in; (void)out_size;

    cudaFuncSetAttribute(qkv_mma_kernel,
                         cudaFuncAttributeMaxDynamicSharedMemorySize, GSMEM2);
    cudaFuncSetAttribute(oproj_mma_kernel,
                         cudaFuncAttributeMaxDynamicSharedMemorySize, GSMEM2);
    cudaFuncSetAttribute(attn_mma_kernel,
                         cudaFuncAttributeMaxDynamicSharedMemorySize, ASMEM2);

    cvt_x_kernel<<<(MROWS * EMBED) / 1024, 256>>>(x);
    cvt_w_kernel<<<dim3(32, 32, 4), dim3(32, 8)>>>(Wq, Wk, Wv, Wo);
    mask_scan_kernel<<<BATCH, 256>>>(mask);

    dim3 gq(EMBED / 128, MROWS / 128, 3);
    qkv_mma_kernel<<<gq, GTH, GSMEM2>>>(bq, bk, bv, mask);

    dim3 ga(SEQ / 64, NHEAD, BATCH);
    attn_mma_kernel<<<ga, ATH, ASMEM2>>>(mask);

    dim3 go(EMBED / 128, MROWS / 128, 1);
    oproj_mma_kernel<<<go, GTH, GSMEM2>>>(bo, out);
}